// round 2
// baseline (speedup 1.0000x reference)
#include <cuda_runtime.h>
#include <math.h>

#define Bdim 64
#define Tdim 1024
#define Edim 512
#define Hdim 1024
#define Vdim 512

#define NCTA 128
#define THREADS 512

#define KSPLIT 8
#define NSPLIT 16
#define KS 128              // W_hh rows per CTA
#define NS 64               // W_hh cols per CTA
#define HPU 130             // ull pitch of duplicated h tile (128 + pad)
#define APITCH 20           // float pitch of A tiles (16 + pad)

typedef unsigned long long ull;

// ---------------- device scratch (no allocations allowed) ----------------
__device__ __align__(16) float g_xp[Bdim * Tdim * Hdim];        // 256 MB
__device__ __align__(16) float g_hs[Bdim * Tdim * Hdim];        // 256 MB
__device__ __align__(16) float g_h[2][Bdim * Hdim];
__device__ __align__(16) float g_partial[KSPLIT][Bdim * Hdim];
__device__ unsigned g_barrier;   // recurrence grid barrier (monotonic)
__device__ unsigned g_bar_a;     // phase-A grid barrier
__device__ unsigned g_step;      // recurrence progress (steps completed)

// ---------------- f32x2 helpers ----------------
__device__ __forceinline__ ull pack2(float x, float y) {
    ull r;
    asm("mov.b64 %0, {%1, %2};" : "=l"(r) : "r"(__float_as_uint(x)), "r"(__float_as_uint(y)));
    return r;
}
__device__ __forceinline__ void unpack2(ull v, float& x, float& y) {
    unsigned lo, hi;
    asm("mov.b64 {%0, %1}, %2;" : "=r"(lo), "=r"(hi) : "l"(v));
    x = __uint_as_float(lo); y = __uint_as_float(hi);
}
__device__ __forceinline__ ull fma2(ull a, ull b, ull c) {
    ull d;
    asm("fma.rn.f32x2 %0, %1, %2, %3;" : "=l"(d) : "l"(a), "l"(b), "l"(c));
    return d;
}

__device__ __forceinline__ void barn(int id) {
    asm volatile("bar.sync %0, 256;" :: "r"(id) : "memory");
}
__device__ __forceinline__ unsigned ld_acq(const unsigned* p) {
    unsigned v;
    asm volatile("ld.acquire.gpu.u32 %0, [%1];" : "=r"(v) : "l"(p));
    return v;
}

// ---------------- init (every replay) ----------------
__global__ void init_kernel() {
    int i = blockIdx.x * blockDim.x + threadIdx.x;
    if (i == 0) { g_barrier = 0u; g_bar_a = 0u; g_step = 0u; }
    if (i < Bdim * Hdim) g_h[0][i] = 0.0f;
}

// ---------------- shared 16-k MMA micro-kernel: 4m x 8n per thread ----------------
__device__ __forceinline__ void mma16(const float* __restrict__ sa, int arow0,
                                      const float* __restrict__ sb, int txn,
                                      ull acc[4][4])
{
#pragma unroll
    for (int k = 0; k < 16; k++) {
        ulonglong2 w0 = *(const ulonglong2*)&sb[k * 128 + txn * 8];
        ulonglong2 w1 = *(const ulonglong2*)&sb[k * 128 + txn * 8 + 4];
#pragma unroll
        for (int i = 0; i < 4; i++) {
            float a = sa[(arow0 + i) * APITCH + k];
            ull aa = pack2(a, a);
            acc[i][0] = fma2(aa, w0.x, acc[i][0]);
            acc[i][1] = fma2(aa, w0.y, acc[i][1]);
            acc[i][2] = fma2(aa, w1.x, acc[i][2]);
            acc[i][3] = fma2(aa, w1.y, acc[i][3]);
        }
    }
}

// ---------------- recurrence grid barrier (rec half only: named barrier 1) ----------------
__device__ __forceinline__ void gbar(unsigned phase) {
    barn(1);
    if (threadIdx.x == 0) {
        __threadfence();
        atomicAdd(&g_barrier, 1u);
        const unsigned target = phase * (unsigned)NCTA;
        while (ld_acq(&g_barrier) < target) {}
    }
    barn(1);
}

// =====================================================================
// mega kernel: phase A = GEMM1 (all warps); then warps 0-7 recurrence,
// warps 8-15 GEMM2 consuming completed steps via g_step.
// =====================================================================
__global__ void __launch_bounds__(THREADS, 1) mega_kernel(
    const float* __restrict__ X, const float* __restrict__ W_xh,
    const float* __restrict__ b_h, const float* __restrict__ W_hh,
    const float* __restrict__ W_hy, const float* __restrict__ b_y,
    float* __restrict__ Y, float* __restrict__ hfinal)
{
    extern __shared__ float sm[];
    float* sW  = sm;                           // 8192 floats (32 KB)
    ull*   sHd = (ull*)(sm + 8192);            // 8320 ull  (65 KB): duplicated h slice
    float* gA  = sm + 8192 + 8320 * 2;         // 5120 floats: A tiles (2 bufs)
    float* gB  = gA + 5120;                    // 4096 floats: B tiles (2 bufs)

    const int tid = threadIdx.x;

    // ================= PHASE A: xp = X @ W_xh + b_h =================
    {
        const float4* X4  = (const float4*)X;
        const float4* Wx4 = (const float4*)W_xh;
        const int rA = tid >> 2, cA = tid & 3;       // A tile loads: 128 x 4 f4
        const int rB = tid >> 5, cB = tid & 31;      // B tile loads: 16 x 32 f4
        const int txn = tid & 15, tym = tid >> 4;    // out: 32 m-groups x 16 n-groups

        for (int it = 0; it < 32; it++) {
            const int tile = blockIdx.x + NCTA * it;
            const int m0 = (tile >> 3) << 7;
            const int n04 = (tile & 7) << 5;          // n0/4

            // prologue: kt = 0
            *(float4*)&gA[rA * APITCH + cA * 4] = X4[(size_t)(m0 + rA) * 128 + cA];
            *(float4*)&gB[rB * 128 + cB * 4]    = Wx4[(size_t)rB * 256 + n04 + cB];
            __syncthreads();

            ull acc[4][4];
#pragma unroll
            for (int i = 0; i < 4; i++)
#pragma unroll
                for (int j = 0; j < 4; j++) acc[i][j] = 0ull;

            for (int kt = 0; kt < 32; kt++) {
                const int cb = kt & 1;
                float4 pa, pb;
                const bool more = (kt + 1 < 32);
                if (more) {
                    pa = X4[(size_t)(m0 + rA) * 128 + (kt + 1) * 4 + cA];
                    pb = Wx4[(size_t)((kt + 1) * 16 + rB) * 256 + n04 + cB];
                }
                mma16(gA + cb * 2560, tym << 2, gB + cb * 2048, txn, acc);
                if (more) {
                    const int nb = cb ^ 1;
                    *(float4*)&gA[nb * 2560 + rA * APITCH + cA * 4] = pa;
                    *(float4*)&gB[nb * 2048 + rB * 128 + cB * 4]    = pb;
                }
                __syncthreads();
            }

            const int n0 = n04 << 2;
            float4 bv0 = *(const float4*)&b_h[n0 + txn * 8];
            float4 bv1 = *(const float4*)&b_h[n0 + txn * 8 + 4];
#pragma unroll
            for (int i = 0; i < 4; i++) {
                float x0, x1, x2, x3, x4, x5, x6, x7;
                unpack2(acc[i][0], x0, x1); unpack2(acc[i][1], x2, x3);
                unpack2(acc[i][2], x4, x5); unpack2(acc[i][3], x6, x7);
                const size_t row = (size_t)(m0 + (tym << 2) + i);
                *(float4*)&g_xp[row * Hdim + n0 + txn * 8] =
                    make_float4(x0 + bv0.x, x1 + bv0.y, x2 + bv0.z, x3 + bv0.w);
                *(float4*)&g_xp[row * Hdim + n0 + txn * 8 + 4] =
                    make_float4(x4 + bv1.x, x5 + bv1.y, x6 + bv1.z, x7 + bv1.w);
            }
        }

        // phase-A grid barrier (all CTAs, full block)
        __syncthreads();
        if (tid == 0) {
            __threadfence();
            atomicAdd(&g_bar_a, 1u);
            while (ld_acq(&g_bar_a) < (unsigned)NCTA) {}
        }
        __syncthreads();
    }

    // ================= split: warps 0-7 recurrence, warps 8-15 GEMM2 =================
    if (tid < 256) {
        // ---------------- recurrence ----------------
        const int kidx = blockIdx.x >> 4;
        const int nidx = blockIdx.x & 15;
        const int k0 = kidx * KS, n0 = nidx * NS;
        const int tx = tid & 15, ty = tid >> 4;

        // W block resident in SMEM for all steps
        {
            const float4* W4 = (const float4*)W_hh;
#pragma unroll
            for (int i = 0; i < 8; i++) {
                int idx = tid + i * 256;
                int r = idx >> 4, c = idx & 15;
                *(float4*)&sW[r * NS + c * 4] = W4[(size_t)(k0 + r) * 256 + (n0 >> 2) + c];
            }
        }

        const int rbase = blockIdx.x * 512;
        unsigned phase = 0;

        for (int t = 0; t < Tdim; t++) {
            const float* cur = g_h[t & 1];
            float* nxt = g_h[(t + 1) & 1];

            // load h slice, duplicated (f32x2 broadcast operand ready-made)
            {
                const float4* c4p = (const float4*)cur;
#pragma unroll
                for (int i = 0; i < 8; i++) {
                    int idx = tid + i * 256;
                    int b = idx >> 5, c = idx & 31;
                    float4 v = c4p[(size_t)b * 256 + (k0 >> 2) + c];
                    ull* p = &sHd[b * HPU + c * 4];
                    ((ulonglong2*)p)[0] = make_ulonglong2(pack2(v.x, v.x), pack2(v.y, v.y));
                    ((ulonglong2*)p)[1] = make_ulonglong2(pack2(v.z, v.z), pack2(v.w, v.w));
                }
            }
            barn(1);

            ull acc[4][2];
#pragma unroll
            for (int i = 0; i < 4; i++) { acc[i][0] = 0ull; acc[i][1] = 0ull; }

#pragma unroll 8
            for (int k = 0; k < KS; k++) {
                ulonglong2 w = *(const ulonglong2*)&sW[k * NS + tx * 4];
#pragma unroll
                for (int i = 0; i < 4; i++) {
                    ull aa = sHd[(ty * 4 + i) * HPU + k];
                    acc[i][0] = fma2(aa, w.x, acc[i][0]);
                    acc[i][1] = fma2(aa, w.y, acc[i][1]);
                }
            }

            {
                float* pp = g_partial[kidx];
#pragma unroll
                for (int i = 0; i < 4; i++) {
                    float x0, x1, x2, x3;
                    unpack2(acc[i][0], x0, x1);
                    unpack2(acc[i][1], x2, x3);
                    *(float4*)&pp[(size_t)(ty * 4 + i) * Hdim + n0 + tx * 4] =
                        make_float4(x0, x1, x2, x3);
                }
            }
            gbar(++phase);

            // distributed reduce + tanh + publish
            {
                const int f = rbase + tid * 2;
                const int b = f >> 10;
                const int hc = f & (Hdim - 1);
                float s0 = 0.f, s1 = 0.f;
#pragma unroll
                for (int kk = 0; kk < KSPLIT; kk++) {
                    float2 p = *(const float2*)&g_partial[kk][f];
                    s0 += p.x; s1 += p.y;
                }
                const size_t xidx = (size_t)b * Tdim * Hdim + (size_t)t * Hdim + hc;
                const float2 xp = *(const float2*)&g_xp[xidx];
                float v0 = tanhf(s0 + xp.x);
                float v1 = tanhf(s1 + xp.y);
                *(float2*)&nxt[f] = make_float2(v0, v1);
                *(float2*)&g_hs[xidx] = make_float2(v0, v1);
                if (t == Tdim - 1) *(float2*)&hfinal[f] = make_float2(v0, v1);
            }
            gbar(++phase);

            if (blockIdx.x == 0 && tid == 0) {
                asm volatile("st.release.gpu.u32 [%0], %1;"
                             :: "l"(&g_step), "r"((unsigned)(t + 1)) : "memory");
            }
        }
    } else {
        // ---------------- GEMM2: Y = hs @ W_hy + b_y, step-gated ----------------
        const int ltid = tid - 256;
        const int rA = ltid >> 2, cA = ltid & 3;     // A loads: 64 rows x 4 f4
        const int txn = ltid & 15, tym = ltid >> 4;  // out: 16 m-groups x 16 n-groups
        const float4* hs4 = (const float4*)g_hs;
        const float4* Wy4 = (const float4*)W_hy;

        for (int it = 0; it < 32; it++) {
            const int tau = blockIdx.x + NCTA * it;
            const int t = tau >> 2;
            const int n04 = (tau & 3) << 5;           // n0/4, n0 in {0,128,256,384}

            if (ltid == 0) {
                while (ld_acq(&g_step) < (unsigned)(t + 1)) {}
            }
            barn(2);

            // prologue kt = 0
            *(float4*)&gA[rA * APITCH + cA * 4] = hs4[((size_t)rA * Tdim + t) * 256 + cA];
#pragma unroll
            for (int j = 0; j < 2; j++) {
                int idx = ltid + j * 256;
                int rB = idx >> 5, cB = idx & 31;
                *(float4*)&gB[rB * 128 + cB * 4] = Wy4[(size_t)rB * 128 + n04 + cB];
            }
            barn(2);

            ull acc[4][4];
#pragma unroll
            for (int i = 0; i < 4; i++)
#pragma unroll
                for (int j = 0; j < 4; j++) acc[i][j] = 0ull;

            for (int kt = 0; kt < 64; kt++) {
                const int cb = kt & 1;
                float4 pa, pb0, pb1;
                const bool more = (kt + 1 < 64);
                if (more) {
                    pa = hs4[((size_t)rA * Tdim + t) * 256 + (kt + 1) * 4 + cA];
                    {
                        int idx = ltid;
                        int rB = idx >> 5, cB = idx & 31;
                        pb0 = Wy4[(size_t)((kt + 1) * 16 + rB) * 128 + n04 + cB];
                    }
                    {
                        int idx = ltid + 256;
                        int rB = idx >> 5, cB = idx & 31;
                        pb1 = Wy4[(size_t)((kt + 1) * 16 + rB) * 128 + n04 + cB];
                    }
                }
                mma16(gA + cb * 1280, tym << 2, gB + cb * 2048, txn, acc);
                if (more) {
                    const int nb = cb ^ 1;
                    *(float4*)&gA[nb * 1280 + rA * APITCH + cA * 4] = pa;
                    {
                        int idx = ltid;
                        int rB = idx >> 5, cB = idx & 31;
                        *(float4*)&gB[nb * 2048 + rB * 128 + cB * 4] = pb0;
                    }
                    {
                        int idx = ltid + 256;
                        int rB = idx >> 5, cB = idx & 31;
                        *(float4*)&gB[nb * 2048 + rB * 128 + cB * 4] = pb1;
                    }
                }
                barn(2);
            }

            const int n0 = n04 << 2;
            float4 bv0 = *(const float4*)&b_y[n0 + txn * 8];
            float4 bv1 = *(const float4*)&b_y[n0 + txn * 8 + 4];
#pragma unroll
            for (int i = 0; i < 4; i++) {
                float x0, x1, x2, x3, x4, x5, x6, x7;
                unpack2(acc[i][0], x0, x1); unpack2(acc[i][1], x2, x3);
                unpack2(acc[i][2], x4, x5); unpack2(acc[i][3], x6, x7);
                const int b = (tym << 2) + i;
                const size_t row = (size_t)b * Tdim + t;
                *(float4*)&Y[row * Vdim + n0 + txn * 8] =
                    make_float4(x0 + bv0.x, x1 + bv0.y, x2 + bv0.z, x3 + bv0.w);
                *(float4*)&Y[row * Vdim + n0 + txn * 8 + 4] =
                    make_float4(x4 + bv1.x, x5 + bv1.y, x6 + bv1.z, x7 + bv1.w);
            }
        }
    }
}

// ---------------- launch ----------------
extern "C" void kernel_launch(void* const* d_in, const int* in_sizes, int n_in,
                              void* d_out, int out_size)
{
    (void)in_sizes; (void)n_in; (void)out_size;
    const float* X    = (const float*)d_in[0];
    const float* W_xh = (const float*)d_in[1];
    const float* b_h  = (const float*)d_in[2];
    const float* W_hh = (const float*)d_in[3];
    const float* W_hy = (const float*)d_in[4];
    const float* b_y  = (const float*)d_in[5];

    float* Y    = (float*)d_out;
    float* hfin = Y + (size_t)Bdim * Tdim * Vdim;

    init_kernel<<<(Bdim * Hdim + 255) / 256, 256>>>();

    const int shbytes = (8192 + 8320 * 2 + 5120 + 4096) * (int)sizeof(float); // 136192
    cudaFuncSetAttribute(mega_kernel,
                         cudaFuncAttributeMaxDynamicSharedMemorySize, shbytes);
    mega_kernel<<<NCTA, THREADS, shbytes>>>(X, W_xh, b_h, W_hh, W_hy, b_y, Y, hfin);
}

// round 3
// speedup vs baseline: 1.4667x; 1.4667x over previous
#include <cuda_runtime.h>
#include <math.h>

#define Bdim 64
#define Tdim 1024
#define Edim 512
#define Hdim 1024
#define Vdim 512

#define NCTA 128
#define KSPLIT 8
#define NSPLIT 16
#define KS 128              // W_hh rows per CTA
#define NS 64               // W_hh cols per CTA
#define HPU 130             // ull pitch of duplicated h tile

typedef unsigned long long ull;

// ---------------- device scratch (no allocations allowed) ----------------
__device__ __align__(16) float g_xp[Bdim * Tdim * Hdim];        // 256 MB
__device__ __align__(16) float g_hs[Bdim * Tdim * Hdim];        // 256 MB
__device__ __align__(16) float g_h[2][Bdim * Hdim];
__device__ __align__(16) float g_partial[KSPLIT][Bdim * Hdim];
__device__ unsigned g_barrier;

// ---------------- f32x2 helpers ----------------
__device__ __forceinline__ ull pack2(float x, float y) {
    ull r;
    asm("mov.b64 %0, {%1, %2};" : "=l"(r) : "r"(__float_as_uint(x)), "r"(__float_as_uint(y)));
    return r;
}
__device__ __forceinline__ void unpack2(ull v, float& x, float& y) {
    unsigned lo, hi;
    asm("mov.b64 {%0, %1}, %2;" : "=r"(lo), "=r"(hi) : "l"(v));
    x = __uint_as_float(lo); y = __uint_as_float(hi);
}
__device__ __forceinline__ ull fma2(ull a, ull b, ull c) {
    ull d;
    asm("fma.rn.f32x2 %0, %1, %2, %3;" : "=l"(d) : "l"(a), "l"(b), "l"(c));
    return d;
}
__device__ __forceinline__ unsigned ld_acq(const unsigned* p) {
    unsigned v;
    asm volatile("ld.acquire.gpu.u32 %0, [%1];" : "=r"(v) : "l"(p));
    return v;
}

// ---------------- cp.async helpers ----------------
__device__ __forceinline__ void cpa16(void* dst, const void* src) {
    unsigned d = (unsigned)__cvta_generic_to_shared(dst);
    asm volatile("cp.async.cg.shared.global [%0], [%1], 16;" :: "r"(d), "l"(src));
}
#define CP_COMMIT() asm volatile("cp.async.commit_group;")
#define CP_WAIT0()  asm volatile("cp.async.wait_group 0;")

// ---------------- init (every replay) ----------------
__global__ void init_kernel() {
    int i = blockIdx.x * blockDim.x + threadIdx.x;
    if (i == 0) g_barrier = 0u;
    if (i < Bdim * Hdim) g_h[0][i] = 0.0f;
}

// =====================================================================
// GEMM: C[M,N] = A[M,K] @ B[K,N] + bias[N]
// 128x128x16 tile, 256 threads, 8m x 8n per thread (f32x2), cp.async DB.
// =====================================================================
__global__ void __launch_bounds__(256, 2) gemm128(
    const float* __restrict__ A, const float* __restrict__ Bm,
    const float* __restrict__ bias, float* __restrict__ C,
    int M, int N, int K)
{
    __shared__ float sA[2][128 * 20];   // [m][k], pitch 20 (16B-aligned, bank-safe)
    __shared__ float sB[2][16 * 128];   // [k][n]

    const int tid = threadIdx.x;
    const int tx = tid & 15;            // n-group: cols 8*tx .. 8*tx+7
    const int ty = tid >> 4;            // m rows: ty + 16*i
    const int m0 = blockIdx.y * 128;
    const int n0 = blockIdx.x * 128;
    const int nk = K >> 4;

    // stage loader: 4 x cp.async(16B) per thread
    const int rA = tid >> 2, cA = (tid & 3) << 2;         // A: 128 rows x 4 f4
    const int rB0 = tid >> 5, cB0 = (tid & 31) << 2;      // B: 16 rows x 32 f4 (2 halves)

#define LOAD_STAGE(buf, kt)                                                         \
    do {                                                                            \
        cpa16(&sA[buf][rA * 20 + cA], &A[(size_t)(m0 + rA) * K + (kt) * 16 + cA]);  \
        cpa16(&sA[buf][(rA + 64) * 20 + cA],                                        \
              &A[(size_t)(m0 + rA + 64) * K + (kt) * 16 + cA]);                     \
        cpa16(&sB[buf][rB0 * 128 + cB0],                                            \
              &Bm[(size_t)((kt) * 16 + rB0) * N + n0 + cB0]);                       \
        cpa16(&sB[buf][(rB0 + 8) * 128 + cB0],                                      \
              &Bm[(size_t)((kt) * 16 + rB0 + 8) * N + n0 + cB0]);                   \
        CP_COMMIT();                                                                \
    } while (0)

    LOAD_STAGE(0, 0);
    CP_WAIT0();
    __syncthreads();

    ull acc[8][4];
#pragma unroll
    for (int i = 0; i < 8; i++)
#pragma unroll
        for (int j = 0; j < 4; j++) acc[i][j] = 0ull;

    for (int kt = 0; kt < nk; kt++) {
        const int buf = kt & 1;
        if (kt + 1 < nk) LOAD_STAGE(buf ^ 1, kt + 1);

#pragma unroll
        for (int k = 0; k < 16; k++) {
            ulonglong2 w0 = *(const ulonglong2*)&sB[buf][k * 128 + tx * 8];
            ulonglong2 w1 = *(const ulonglong2*)&sB[buf][k * 128 + tx * 8 + 4];
#pragma unroll
            for (int i = 0; i < 8; i++) {
                float a = sA[buf][(ty + 16 * i) * 20 + k];
                ull aa = pack2(a, a);
                acc[i][0] = fma2(aa, w0.x, acc[i][0]);
                acc[i][1] = fma2(aa, w0.y, acc[i][1]);
                acc[i][2] = fma2(aa, w1.x, acc[i][2]);
                acc[i][3] = fma2(aa, w1.y, acc[i][3]);
            }
        }
        CP_WAIT0();
        __syncthreads();
    }
#undef LOAD_STAGE

    const float4 bv0 = *(const float4*)&bias[n0 + tx * 8];
    const float4 bv1 = *(const float4*)&bias[n0 + tx * 8 + 4];
#pragma unroll
    for (int i = 0; i < 8; i++) {
        float x0, x1, x2, x3, x4, x5, x6, x7;
        unpack2(acc[i][0], x0, x1); unpack2(acc[i][1], x2, x3);
        unpack2(acc[i][2], x4, x5); unpack2(acc[i][3], x6, x7);
        const size_t row = (size_t)(m0 + ty + 16 * i);
        *(float4*)&C[row * N + n0 + tx * 8] =
            make_float4(x0 + bv0.x, x1 + bv0.y, x2 + bv0.z, x3 + bv0.w);
        *(float4*)&C[row * N + n0 + tx * 8 + 4] =
            make_float4(x4 + bv1.x, x5 + bv1.y, x6 + bv1.z, x7 + bv1.w);
    }
}

// =====================================================================
// recurrence: 1024 steps of h = tanh(xp_t + h @ W_hh)
// 128 CTAs x 512 threads, KSPLIT=8 x NSPLIT=16, two grid barriers/step.
// =====================================================================
__global__ void __launch_bounds__(512, 1) rnn_recurrence(
    const float* __restrict__ W_hh, float* __restrict__ hfinal)
{
    extern __shared__ float sm[];
    float* sW  = sm;                     // [128][64]  32 KB
    ull*   sHd = (ull*)(sm + KS * NS);   // [64][130]  65 KB (duplicated f32x2)

    const int tid = threadIdx.x;
    const int kidx = blockIdx.x >> 4;
    const int nidx = blockIdx.x & 15;
    const int k0 = kidx * KS, n0 = nidx * NS;
    const int tx = tid & 15;             // n: 4 floats at n0 + tx*4
    const int ty = tid >> 4;             // m: rows 2*ty, 2*ty+1

    // W block resident for all steps
    {
        const float4* W4 = (const float4*)W_hh;
#pragma unroll
        for (int i = 0; i < 4; i++) {
            int idx = tid + i * 512;
            int r = idx >> 4, c = idx & 15;
            *(float4*)&sW[r * NS + c * 4] = W4[(size_t)(k0 + r) * 256 + (n0 >> 2) + c];
        }
    }

    const int rbase = blockIdx.x * 512;
    unsigned phase = 0;

    for (int t = 0; t < Tdim; t++) {
        const float* cur = g_h[t & 1];
        float* nxt = g_h[(t + 1) & 1];

        // load h slice duplicated: sHd[b][k] = (h,h)
        {
            const float4* c4p = (const float4*)cur;
#pragma unroll
            for (int i = 0; i < 4; i++) {
                int idx = tid + i * 512;
                int b = idx >> 5, c = idx & 31;
                float4 v = c4p[(size_t)b * 256 + (k0 >> 2) + c];
                ull* p = &sHd[b * HPU + c * 4];
                ((ulonglong2*)p)[0] = make_ulonglong2(pack2(v.x, v.x), pack2(v.y, v.y));
                ((ulonglong2*)p)[1] = make_ulonglong2(pack2(v.z, v.z), pack2(v.w, v.w));
            }
        }
        __syncthreads();

        // partial(2x4 per thread) = hslice(64x128) @ Wblock(128x64)
        ull a00 = 0ull, a01 = 0ull, a10 = 0ull, a11 = 0ull;
#pragma unroll 16
        for (int k = 0; k < KS; k++) {
            ulonglong2 w = *(const ulonglong2*)&sW[k * NS + tx * 4];
            ull aa0 = sHd[(ty * 2) * HPU + k];
            ull aa1 = sHd[(ty * 2 + 1) * HPU + k];
            a00 = fma2(aa0, w.x, a00);
            a01 = fma2(aa0, w.y, a01);
            a10 = fma2(aa1, w.x, a10);
            a11 = fma2(aa1, w.y, a11);
        }

        // write 2 partial rows
        {
            float* pp = g_partial[kidx];
            float x0, x1, x2, x3;
            unpack2(a00, x0, x1); unpack2(a01, x2, x3);
            *(float4*)&pp[(size_t)(ty * 2) * Hdim + n0 + tx * 4] =
                make_float4(x0, x1, x2, x3);
            unpack2(a10, x0, x1); unpack2(a11, x2, x3);
            *(float4*)&pp[(size_t)(ty * 2 + 1) * Hdim + n0 + tx * 4] =
                make_float4(x0, x1, x2, x3);
        }

        // barrier 1: partials visible
        __syncthreads();
        if (tid == 0) {
            __threadfence();
            atomicAdd(&g_barrier, 1u);
            const unsigned target = (++phase) * (unsigned)NCTA;
            while (ld_acq(&g_barrier) < target) {}
        } else ++phase;
        __syncthreads();

        // distributed reduce + tanh + publish (1 elem/thread)
        {
            const int f = rbase + tid;
            const int b = f >> 10;
            const int hc = f & (Hdim - 1);
            float s = 0.f;
#pragma unroll
            for (int kk = 0; kk < KSPLIT; kk++) s += g_partial[kk][f];
            const size_t xidx = (size_t)b * Tdim * Hdim + (size_t)t * Hdim + hc;
            float v = tanhf(s + g_xp[xidx]);
            nxt[f] = v;
            g_hs[xidx] = v;
            if (t == Tdim - 1) hfinal[f] = v;
        }

        // barrier 2: h(t+1) visible
        __syncthreads();
        if (tid == 0) {
            __threadfence();
            atomicAdd(&g_barrier, 1u);
            const unsigned target = (++phase) * (unsigned)NCTA;
            while (ld_acq(&g_barrier) < target) {}
        } else ++phase;
        __syncthreads();
    }
}

// ---------------- launch ----------------
extern "C" void kernel_launch(void* const* d_in, const int* in_sizes, int n_in,
                              void* d_out, int out_size)
{
    (void)in_sizes; (void)n_in; (void)out_size;
    const float* X    = (const float*)d_in[0];
    const float* W_xh = (const float*)d_in[1];
    const float* b_h  = (const float*)d_in[2];
    const float* W_hh = (const float*)d_in[3];
    const float* W_hy = (const float*)d_in[4];
    const float* b_y  = (const float*)d_in[5];

    float* Y    = (float*)d_out;
    float* hfin = Y + (size_t)Bdim * Tdim * Vdim;

    float *pxp = nullptr, *phs = nullptr;
    cudaGetSymbolAddress((void**)&pxp, g_xp);
    cudaGetSymbolAddress((void**)&phs, g_hs);

    init_kernel<<<(Bdim * Hdim + 255) / 256, 256>>>();

    // GEMM1: xp = X @ W_xh + b_h   (M=65536, N=1024, K=512)
    dim3 g1(Hdim / 128, (Bdim * Tdim) / 128);
    gemm128<<<g1, 256>>>(X, W_xh, b_h, pxp, Bdim * Tdim, Hdim, Edim);

    // recurrence
    const int shbytes = (KS * NS) * 4 + (Bdim * HPU) * 8;   // 32768 + 66560 = 99328
    cudaFuncSetAttribute(rnn_recurrence,
                         cudaFuncAttributeMaxDynamicSharedMemorySize, shbytes);
    rnn_recurrence<<<NCTA, 512, shbytes>>>(W_hh, hfin);

    // GEMM2: Y = hs @ W_hy + b_y   (M=65536, N=512, K=1024)
    dim3 g2(Vdim / 128, (Bdim * Tdim) / 128);
    gemm128<<<g2, 256>>>(phs, W_hy, b_y, Y, Bdim * Tdim, Vdim, Hdim);
}